// round 15
// baseline (speedup 1.0000x reference)
#include <cuda_runtime.h>
#include <math.h>

// Problem constants
#define BATCH 64
#define TSTEPS 512
#define DDIM 128
#define HDIM 1024
#define GRID 128          // 16 n-tiles x 8 k-splits
#define KCHUNK 128
#define NTILE 64

// Rotating accumulator buffers: 3*64*1024*4B = 768 KB (static, zero-init)
__device__ float g_acc[3][BATCH][HDIM];
// Monotonic grid-barrier ticket (never reset; wrap-safe compare)
__device__ unsigned g_count;

// ---------------------------------------------------------------------------
// tf32 helpers
// ---------------------------------------------------------------------------
__device__ __forceinline__ unsigned f2tf32(float x) {
    unsigned u;
    asm("cvt.rna.tf32.f32 %0, %1;" : "=r"(u) : "f"(x));
    return u;
}

__device__ __forceinline__ void mma_tf32(
    float c[4], unsigned a0, unsigned a1, unsigned a2, unsigned a3,
    unsigned b0, unsigned b1)
{
    asm volatile(
        "mma.sync.aligned.m16n8k8.row.col.f32.tf32.tf32.f32 "
        "{%0,%1,%2,%3}, {%4,%5,%6,%7}, {%8,%9}, {%0,%1,%2,%3};"
        : "+f"(c[0]), "+f"(c[1]), "+f"(c[2]), "+f"(c[3])
        : "r"(a0), "r"(a1), "r"(a2), "r"(a3), "r"(b0), "r"(b1));
}

// ---------------------------------------------------------------------------
// Kernel A: xp = x @ Wx + b  -> out[B,T,H]   (M=32768, K=128, N=1024)
// ---------------------------------------------------------------------------
__global__ __launch_bounds__(256) void xp_kernel(
    const float* __restrict__ x,
    const float* __restrict__ Wx,
    const float* __restrict__ bias,
    float* __restrict__ out)
{
    __shared__ float xs[64][33];
    __shared__ float ws[32][68];

    const int bx = blockIdx.x;
    const int by = blockIdx.y;
    const int tid = threadIdx.x;
    const int tx = tid & 15;
    const int ty = tid >> 4;
    const int row0 = by * 64;
    const int col0 = bx * 64;

    float acc[4][4];
#pragma unroll
    for (int i = 0; i < 4; i++)
#pragma unroll
        for (int j = 0; j < 4; j++) acc[i][j] = 0.0f;

    for (int k0 = 0; k0 < DDIM; k0 += 32) {
        for (int i = tid; i < 512; i += 256) {
            int m = i >> 3;
            int c = (i & 7) << 2;
            float4 v = *(const float4*)&x[(size_t)(row0 + m) * DDIM + k0 + c];
            xs[m][c + 0] = v.x; xs[m][c + 1] = v.y;
            xs[m][c + 2] = v.z; xs[m][c + 3] = v.w;
        }
        for (int i = tid; i < 512; i += 256) {
            int k = i >> 4;
            int c = (i & 15) << 2;
            *(float4*)&ws[k][c] =
                *(const float4*)&Wx[(size_t)(k0 + k) * HDIM + col0 + c];
        }
        __syncthreads();

#pragma unroll
        for (int kk = 0; kk < 32; kk++) {
            float a[4], bv[4];
#pragma unroll
            for (int i = 0; i < 4; i++) a[i] = xs[ty * 4 + i][kk];
#pragma unroll
            for (int j = 0; j < 4; j++) bv[j] = ws[kk][tx * 4 + j];
#pragma unroll
            for (int i = 0; i < 4; i++)
#pragma unroll
                for (int j = 0; j < 4; j++)
                    acc[i][j] = fmaf(a[i], bv[j], acc[i][j]);
        }
        __syncthreads();
    }

#pragma unroll
    for (int i = 0; i < 4; i++) {
        int row = row0 + ty * 4 + i;
#pragma unroll
        for (int j = 0; j < 4; j++) {
            int col = col0 + tx * 4 + j;
            out[(size_t)row * HDIM + col] = acc[i][j] + bias[col];
        }
    }
}

// ---------------------------------------------------------------------------
// Kernel B: persistent recurrence, single grid barrier per step.
// 128 blocks = (16 n-tiles nb) x (8 k-splits ks). Phase t for block (nb,ks):
//   [nb==0: deferred write of h_{t-1} from smem to out]
//   combine (redundant per ks-group): s = tanh(xp_t + g_acc[br]) for the
//       full 64 x KCHUNK A-chunk; store interleaved into smem
//   zero own 2KB slice of g_acc[bz]
//   __syncthreads
//   tf32 3-term mma GEMM; commit fragments with atomicAdd (REDG) into g_acc[bw]
//   prefetch xp_{t+1} into registers
//   fence + grid barrier
// Buffers rotate (br,bw,bz): written at t==b (mod 3), read at t==b+1,
// zeroed at t==b+2. Epilogue re-zeroes all for graph-replay safety.
// Interleaved smem float2 pairs {v[k], v[k+4]} make every mma fragment load
// a single LDS.64.
// ---------------------------------------------------------------------------
struct SmemLayout {
    float2 hs2[64][66];     // A chunk: hs2[m][4g+c] = {h[m][8g+c], h[m][8g+4+c]}
    float2 wh2[64][66];     // Wh hi bits, transposed [n][...], same interleave
    float2 wl2[64][66];     // Wh lo bits
};

__global__ void __launch_bounds__(256, 1) rnn_persistent(
    float* __restrict__ out,
    const float* __restrict__ Wh)
{
    extern __shared__ char smem_raw[];
    SmemLayout* sm = reinterpret_cast<SmemLayout*>(smem_raw);

    const int bx = blockIdx.x;
    const int ks = bx >> 4;          // 0..7  k-split
    const int nb = bx & 15;          // 0..15 n-tile
    const int k0 = ks * KCHUNK;
    const int n0 = nb * NTILE;
    const int tid = threadIdx.x;
    const int w  = tid >> 5;         // warp 0..7
    const int ln = tid & 31;
    const int wm = w >> 1;           // m-tile (rows wm*16..wm*16+15)
    const int wn = w & 1;            // n-half (cols wn*32..wn*32+31)
    const int frow = ln >> 2;        // 0..7
    const int fcol = ln & 3;         // 0..3

    // ---- one-time: split Wh tile to tf32 hi/lo, interleaved transpose ----
    for (int i = tid; i < KCHUNK * NTILE; i += 256) {
        int k = i >> 6;              // 0..127
        int n = i & 63;              // 0..63
        float v = Wh[(size_t)(k0 + k) * HDIM + n0 + n];
        unsigned hi = f2tf32(v);
        unsigned lo = f2tf32(v - __uint_as_float(hi));
        int g = k >> 3, pos = k & 7;
        ((float*)&sm->wh2[n][4 * g + (pos & 3)])[pos >> 2] = __uint_as_float(hi);
        ((float*)&sm->wl2[n][4 * g + (pos & 3)])[pos >> 2] = __uint_as_float(lo);
    }
    __syncthreads();

    // Combine mapping: thread -> row m, column segment (4 g-groups)
    const int cm    = tid >> 2;          // 0..63
    const int gbase = (tid & 3) * 4;     // g in gbase..gbase+3
    const size_t rowb = (size_t)cm * TSTEPS * HDIM;

    // Buffer rotation state
    int br = 2, bw = 0, bz = 1;

    // Prefetch xp for t = 0
    float4 xf[8];
#pragma unroll
    for (int gi = 0; gi < 4; gi++) {
        const float4* p = (const float4*)&out[rowb + k0 + 8 * (gbase + gi)];
        xf[2 * gi]     = __ldcg(p);
        xf[2 * gi + 1] = __ldcg(p + 1);
    }

    for (int t = 0; t < TSTEPS; t++) {
        // ---- deferred write of h_{t-1} (nb==0 blocks only) ----
        if (t > 0 && nb == 0) {
#pragma unroll
            for (int gi = 0; gi < 4; gi++) {
                int g = gbase + gi;
                float2 p0 = sm->hs2[cm][4 * g + 0];
                float2 p1 = sm->hs2[cm][4 * g + 1];
                float2 p2 = sm->hs2[cm][4 * g + 2];
                float2 p3 = sm->hs2[cm][4 * g + 3];
                float4* op = (float4*)&out[rowb + (size_t)(t - 1) * HDIM
                                           + k0 + 8 * g];
                op[0] = make_float4(p0.x, p1.x, p2.x, p3.x);
                op[1] = make_float4(p0.y, p1.y, p2.y, p3.y);
            }
        }
        __syncthreads();   // protect hs2 before overwrite (uniform)

        // ---- combine: s = tanh(xp + acc), store interleaved ----
#pragma unroll
        for (int gi = 0; gi < 4; gi++) {
            int g = gbase + gi;
            float4 lo = xf[2 * gi], hi = xf[2 * gi + 1];
            if (t > 0) {
                const float4* ap = (const float4*)&g_acc[br][cm][k0 + 8 * g];
                float4 alo = __ldcg(ap), ahi = __ldcg(ap + 1);
                lo.x += alo.x; lo.y += alo.y; lo.z += alo.z; lo.w += alo.w;
                hi.x += ahi.x; hi.y += ahi.y; hi.z += ahi.z; hi.w += ahi.w;
            }
            lo.x = tanhf(lo.x); lo.y = tanhf(lo.y);
            lo.z = tanhf(lo.z); lo.w = tanhf(lo.w);
            hi.x = tanhf(hi.x); hi.y = tanhf(hi.y);
            hi.z = tanhf(hi.z); hi.w = tanhf(hi.w);
            float4* hp = (float4*)&sm->hs2[cm][4 * g];
            hp[0] = make_float4(lo.x, hi.x, lo.y, hi.y);
            hp[1] = make_float4(lo.z, hi.z, lo.w, hi.w);
        }

        // ---- zero own slice of next-next write buffer ----
        if (t < TSTEPS - 1) {
            float2* zp = (float2*)((float*)g_acc[bz] + bx * 512);
            zp[tid] = make_float2(0.0f, 0.0f);
        }
        __syncthreads();

        if (t < TSTEPS - 1) {
            // ---- tf32 3-term mma GEMM ----
            float c[4][4];
#pragma unroll
            for (int j = 0; j < 4; j++)
#pragma unroll
                for (int i = 0; i < 4; i++) c[j][i] = 0.0f;

            const int ar = wm * 16 + frow;
#pragma unroll 4
            for (int g = 0; g < 16; g++) {
                float2 A0 = sm->hs2[ar][4 * g + fcol];
                float2 A1 = sm->hs2[ar + 8][4 * g + fcol];
                unsigned ah0 = f2tf32(A0.x), ah1 = f2tf32(A1.x);
                unsigned ah2 = f2tf32(A0.y), ah3 = f2tf32(A1.y);
                unsigned al0 = f2tf32(A0.x - __uint_as_float(ah0));
                unsigned al1 = f2tf32(A1.x - __uint_as_float(ah1));
                unsigned al2 = f2tf32(A0.y - __uint_as_float(ah2));
                unsigned al3 = f2tf32(A1.y - __uint_as_float(ah3));
#pragma unroll
                for (int j = 0; j < 4; j++) {
                    const int nn = wn * 32 + j * 8 + frow;
                    float2 BH = sm->wh2[nn][4 * g + fcol];
                    float2 BL = sm->wl2[nn][4 * g + fcol];
                    unsigned bh0 = __float_as_uint(BH.x);
                    unsigned bh1 = __float_as_uint(BH.y);
                    unsigned bl0 = __float_as_uint(BL.x);
                    unsigned bl1 = __float_as_uint(BL.y);
                    mma_tf32(c[j], ah0, ah1, ah2, ah3, bh0, bh1);
                    mma_tf32(c[j], al0, al1, al2, al3, bh0, bh1);
                    mma_tf32(c[j], ah0, ah1, ah2, ah3, bl0, bl1);
                }
            }

            // ---- commit fragments: REDG accumulate into g_acc[bw] ----
            {
                const int m0 = wm * 16 + frow;
                const int cb = n0 + wn * 32 + fcol * 2;
#pragma unroll
                for (int j = 0; j < 4; j++) {
                    atomicAdd(&g_acc[bw][m0][cb + j * 8],         c[j][0]);
                    atomicAdd(&g_acc[bw][m0][cb + j * 8 + 1],     c[j][1]);
                    atomicAdd(&g_acc[bw][m0 + 8][cb + j * 8],     c[j][2]);
                    atomicAdd(&g_acc[bw][m0 + 8][cb + j * 8 + 1], c[j][3]);
                }
            }

            // ---- prefetch xp for next step ----
#pragma unroll
            for (int gi = 0; gi < 4; gi++) {
                const float4* p = (const float4*)
                    &out[rowb + (size_t)(t + 1) * HDIM + k0 + 8 * (gbase + gi)];
                xf[2 * gi]     = __ldcg(p);
                xf[2 * gi + 1] = __ldcg(p + 1);
            }
        }

        // ---- single grid barrier (monotonic ticket; replay-safe) ----
        __threadfence();
        __syncthreads();
        if (tid == 0) {
            unsigned tk = atomicAdd(&g_count, 1u);
            unsigned target = ((tk >> 7) + 1u) << 7;     // 128 arrivals
            while ((int)(*(volatile unsigned*)&g_count) - (int)target < 0) { }
            __threadfence();
        }
        __syncthreads();

        // rotate buffers: next step's (br,bw,bz)
        int obr = br; br = bw; bw = bz; bz = obr;
    }

    // ---- epilogue: write h_511; re-zero all buffers for next replay ----
    if (nb == 0) {
#pragma unroll
        for (int gi = 0; gi < 4; gi++) {
            int g = gbase + gi;
            float2 p0 = sm->hs2[cm][4 * g + 0];
            float2 p1 = sm->hs2[cm][4 * g + 1];
            float2 p2 = sm->hs2[cm][4 * g + 2];
            float2 p3 = sm->hs2[cm][4 * g + 3];
            float4* op = (float4*)&out[rowb + (size_t)(TSTEPS - 1) * HDIM
                                       + k0 + 8 * g];
            op[0] = make_float4(p0.x, p1.x, p2.x, p3.x);
            op[1] = make_float4(p0.y, p1.y, p2.y, p3.y);
        }
    }
#pragma unroll
    for (int b = 0; b < 3; b++) {
        float2* zp = (float2*)((float*)g_acc[b] + bx * 512);
        zp[tid] = make_float2(0.0f, 0.0f);
    }
}

// ---------------------------------------------------------------------------
// kernel_launch: 2 graph nodes total.
// ---------------------------------------------------------------------------
extern "C" void kernel_launch(void* const* d_in, const int* in_sizes, int n_in,
                              void* d_out, int out_size)
{
    (void)in_sizes; (void)n_in; (void)out_size;
    const float* x    = (const float*)d_in[0];
    const float* Wx   = (const float*)d_in[1];
    const float* Wh   = (const float*)d_in[2];
    const float* bias = (const float*)d_in[3];
    float* out = (float*)d_out;

    // 1) xp = x @ Wx + b  -> out
    dim3 gridA(HDIM / 64, (BATCH * TSTEPS) / 64);
    xp_kernel<<<gridA, 256>>>(x, Wx, bias, out);

    // 2) persistent recurrence (single launch, one grid barrier per step)
    cudaFuncSetAttribute(rnn_persistent,
                         cudaFuncAttributeMaxDynamicSharedMemorySize,
                         (int)sizeof(SmemLayout));
    rnn_persistent<<<GRID, 256, sizeof(SmemLayout)>>>(out, Wh);
}